// round 7
// baseline (speedup 1.0000x reference)
#include <cuda_runtime.h>
#include <cuda_bf16.h>
#include <cstdint>

// position_encoder: out[b,s,j] = x[b,s,j] + (j even ? sin : cos)(s / 10000^((j+1)/1024))
// B=4, S=8192, D=1024, fp32.
// Bulk-async (TMA) streaming pipeline: per block 8 rows x 4 batches.
// Stage = one s-row across 4 batches (16KB). 3 load buffers (mbarrier
// complete_tx), compute = pos rotation add (smem->smem), 2 store buffers
// drained via bulk_group commit/wait. In-flight depth lives in SMEM (48KB/block),
// not registers.

#define PE_S        8192
#define PE_D        1024
#define PE_B        4
#define PE_CHUNK    8
#define ROW_BYTES   (PE_D * 4)            // 4096
#define STAGE_BYTES (PE_B * ROW_BYTES)    // 16384
#define N_LDBUF     3
#define N_STBUF     2
#define SMEM_MBAR   0                     // 3 x 8B mbarriers
#define SMEM_LD     1024
#define SMEM_ST     (SMEM_LD + N_LDBUF * STAGE_BYTES)   // 1024 + 49152
#define SMEM_TOTAL  (SMEM_ST + N_STBUF * STAGE_BYTES)   // + 32768 = 82944

// ---- compile-time tables: fd_j = 10000^(-(j+1)/1024), sin(fd_j), cos(fd_j) ----
struct PETab {
    double fd[PE_D];
    float  sf[PE_D];
    float  cf[PE_D];
};
constexpr double cexp_small(double t) {
    double r = 1.0;
    for (int k = 24; k >= 1; --k) r = 1.0 + t * r / (double)k;
    return r;
}
constexpr double csin(double x) {
    double x2 = x * x, term = x, sum = x;
    for (int k = 1; k <= 12; ++k) { term *= -x2 / (double)((2 * k) * (2 * k + 1)); sum += term; }
    return sum;
}
constexpr double ccos(double x) {
    double x2 = x * x, term = 1.0, sum = 1.0;
    for (int k = 1; k <= 12; ++k) { term *= -x2 / (double)((2 * k - 1) * (2 * k)); sum += term; }
    return sum;
}
constexpr PETab make_tab() {
    PETab t{};
    const double kexp = 13.287712379549449 / 1024.0;  // log2(10000)/1024
    const double ln2  = 0.6931471805599453;
    for (int j = 0; j < PE_D; ++j) {
        const double e = (double)(j + 1) * kexp;
        const int    n = (int)e;
        const double f = e - (double)n;
        double v = cexp_small(-f * ln2);
        for (int i = 0; i < n; ++i) v *= 0.5;
        t.fd[j] = v;
        t.sf[j] = (float)csin(v);
        t.cf[j] = (float)ccos(v);
    }
    return t;
}
__device__ constexpr PETab g_tab = make_tab();

// ---- PTX helpers ----
__device__ __forceinline__ uint32_t smem_u32(const void* p) {
    uint32_t a;
    asm("{ .reg .u64 t; cvta.to.shared.u64 t, %1; cvt.u32.u64 %0, t; }" : "=r"(a) : "l"(p));
    return a;
}
__device__ __forceinline__ void mbar_init(uint32_t mbar, uint32_t cnt) {
    asm volatile("mbarrier.init.shared.b64 [%0], %1;" :: "r"(mbar), "r"(cnt) : "memory");
}
__device__ __forceinline__ void mbar_expect_tx(uint32_t mbar, uint32_t bytes) {
    asm volatile("mbarrier.arrive.expect_tx.shared.b64 _, [%0], %1;" :: "r"(mbar), "r"(bytes) : "memory");
}
__device__ __forceinline__ void mbar_wait(uint32_t mbar, uint32_t parity) {
    asm volatile(
        "{\n\t.reg .pred P;\n"
        "W%=:\n\t"
        "mbarrier.try_wait.parity.acquire.cta.shared::cta.b64 P, [%0], %1, 0x989680;\n\t"
        "@!P bra W%=;\n\t}"
        :: "r"(mbar), "r"(parity) : "memory");
}
__device__ __forceinline__ void bulk_g2s(uint32_t sdst, const void* gsrc, uint32_t bytes, uint32_t mbar) {
    asm volatile(
        "cp.async.bulk.shared::cluster.global.mbarrier::complete_tx::bytes [%0], [%1], %2, [%3];"
        :: "r"(sdst), "l"(gsrc), "r"(bytes), "r"(mbar) : "memory");
}
__device__ __forceinline__ void bulk_s2g(void* gdst, uint32_t ssrc, uint32_t bytes) {
    asm volatile(
        "cp.async.bulk.global.shared::cta.bulk_group [%0], [%1], %2;"
        :: "l"(gdst), "r"(ssrc), "r"(bytes) : "memory");
}
__device__ __forceinline__ void bulk_commit() {
    asm volatile("cp.async.bulk.commit_group;" ::: "memory");
}
template <int N>
__device__ __forceinline__ void bulk_wait_read() {
    asm volatile("cp.async.bulk.wait_group.read %0;" :: "n"(N) : "memory");
}
__device__ __forceinline__ void fence_proxy_async() {
    asm volatile("fence.proxy.async;" ::: "memory");
}

__global__ __launch_bounds__(256)
void position_encoder_kernel(const float* __restrict__ x, float* __restrict__ out) {
    extern __shared__ char smem[];
    const uint32_t sbase = smem_u32(smem);
    const int tid = threadIdx.x;
    const int s0  = blockIdx.x * PE_CHUNK;
    const int j0  = tid * 4;

    // init mbarriers + prologue loads (stages 0..N_LDBUF-1)
    if (tid == 0) {
        for (int d = 0; d < N_LDBUF; d++) mbar_init(sbase + SMEM_MBAR + d * 8, 1);
    }
    __syncthreads();
    if (tid == 0) {
        for (int d = 0; d < N_LDBUF; d++) {
            const uint32_t mbar = sbase + SMEM_MBAR + d * 8;
            mbar_expect_tx(mbar, STAGE_BYTES);
            const uint32_t dst = sbase + SMEM_LD + d * STAGE_BYTES;
#pragma unroll
            for (int b = 0; b < PE_B; b++)
                bulk_g2s(dst + b * ROW_BYTES,
                         x + ((size_t)b * PE_S + (size_t)(s0 + d)) * PE_D,
                         ROW_BYTES, mbar);
        }
    }

    // seed sin/cos at s0 (fp64 argument) + per-step rotation coefficients
    float sn[4], cs[4], sf[4], cf[4];
#pragma unroll
    for (int c = 0; c < 4; c++) {
        sincosf((float)((double)s0 * g_tab.fd[j0 + c]), &sn[c], &cs[c]);
        sf[c] = g_tab.sf[j0 + c];
        cf[c] = g_tab.cf[j0 + c];
    }

#pragma unroll 1
    for (int i = 0; i < PE_CHUNK; i++) {
        const int buf = i % N_LDBUF;
        const uint32_t ph = (uint32_t)((i / N_LDBUF) & 1);
        const uint32_t mbar = sbase + SMEM_MBAR + buf * 8;

        // store-buffer recycle gate: stage i reuses stbuf[i&1] written at stage i-2
        if (tid == 0 && i >= N_STBUF) bulk_wait_read<1>();
        mbar_wait(mbar, ph);                 // load data ready (acquire)
        __syncthreads();                     // orders tid0's wait_group before STS

        const float4 p = make_float4(sn[0], cs[1], sn[2], cs[3]);
        const float4* __restrict__ lp =
            reinterpret_cast<const float4*>(smem + SMEM_LD + buf * STAGE_BYTES) + tid;
        float4* __restrict__ sp =
            reinterpret_cast<float4*>(smem + SMEM_ST + (i & 1) * STAGE_BYTES) + tid;
#pragma unroll
        for (int b = 0; b < PE_B; b++) {
            float4 v = lp[b * (ROW_BYTES / 16)];
            v.x += p.x; v.y += p.y; v.z += p.z; v.w += p.w;
            sp[b * (ROW_BYTES / 16)] = v;
        }

        // rotate phase for next row: sin(a+f), cos(a+f)
#pragma unroll
        for (int c = 0; c < 4; c++) {
            const float ns = fmaf(sn[c], cf[c],  cs[c] * sf[c]);
            const float nc = fmaf(cs[c], cf[c], -sn[c] * sf[c]);
            sn[c] = ns; cs[c] = nc;
        }

        __syncthreads();                     // all STS done; all LDS of buf done
        if (tid == 0) {
            fence_proxy_async();             // generic STS -> async-proxy read
            const uint32_t ssrc = sbase + SMEM_ST + (uint32_t)(i & 1) * STAGE_BYTES;
#pragma unroll
            for (int b = 0; b < PE_B; b++)
                bulk_s2g(out + ((size_t)b * PE_S + (size_t)(s0 + i)) * PE_D,
                         ssrc + b * ROW_BYTES, ROW_BYTES);
            bulk_commit();                   // one group per stage

            const int nxt = i + N_LDBUF;     // refill the buffer we just consumed
            if (nxt < PE_CHUNK) {
                mbar_expect_tx(mbar, STAGE_BYTES);
                const uint32_t dst = sbase + SMEM_LD + buf * STAGE_BYTES;
#pragma unroll
                for (int b = 0; b < PE_B; b++)
                    bulk_g2s(dst + b * ROW_BYTES,
                             x + ((size_t)b * PE_S + (size_t)(s0 + nxt)) * PE_D,
                             ROW_BYTES, mbar);
            }
        }
    }

    // drain outstanding bulk stores before SMEM is released
    if (tid == 0) bulk_wait_read<0>();
}

extern "C" void kernel_launch(void* const* d_in, const int* in_sizes, int n_in,
                              void* d_out, int out_size) {
    (void)in_sizes; (void)n_in; (void)out_size;
    const float* x = (const float*)d_in[0];
    float* out = (float*)d_out;
    static int configured = 0;
    if (!configured) {
        cudaFuncSetAttribute(position_encoder_kernel,
                             cudaFuncAttributeMaxDynamicSharedMemorySize, SMEM_TOTAL);
        configured = 1;
    }
    position_encoder_kernel<<<PE_S / PE_CHUNK, 256, SMEM_TOTAL>>>(x, out);
}

// round 8
// speedup vs baseline: 1.0914x; 1.0914x over previous
#include <cuda_runtime.h>
#include <cuda_bf16.h>

// position_encoder: out[b,s,j] = x[b,s,j] + (j even ? sin : cos)(s / 10000^((j+1)/1024))
// B=4, S=8192, D=1024, fp32.
// Leanest streaming form: 512-thread blocks, 2 rows/block (thread = row x col4),
// direct per-row sincosf seeding from fp64 theta (no recurrence), 4 batch
// loads front-batched, 4 adds, 4 stores. Compile-time fd table.

#define PE_S     8192
#define PE_D     1024
#define PE_B     4
#define PE_ROWS  2                 // rows per block
#define PE_D4    (PE_D / 4)        // 256 float4 per row

struct PETab { double fd[PE_D]; };

constexpr double cexp_small(double t) {
    double r = 1.0;
    for (int k = 24; k >= 1; --k) r = 1.0 + t * r / (double)k;
    return r;
}
constexpr PETab make_tab() {
    PETab t{};
    const double kexp = 13.287712379549449 / 1024.0;  // log2(10000)/1024
    const double ln2  = 0.6931471805599453;
    for (int j = 0; j < PE_D; ++j) {
        const double e = (double)(j + 1) * kexp;
        const int    n = (int)e;
        const double f = e - (double)n;
        double v = cexp_small(-f * ln2);              // 2^-frac
        for (int i = 0; i < n; ++i) v *= 0.5;         // * 2^-int (exact)
        t.fd[j] = v;
    }
    return t;
}
__device__ constexpr PETab g_tab = make_tab();

__global__ __launch_bounds__(512)
void position_encoder_kernel(const float4* __restrict__ x, float4* __restrict__ out) {
    const int d4  = threadIdx.x & (PE_D4 - 1);        // 0..255 -> column group
    const int r   = threadIdx.x >> 8;                 // 0..1   -> row within block
    const int s   = blockIdx.x * PE_ROWS + r;         // global row
    const int j0  = d4 * 4;

    // pos vector for (s, j0..j0+3): fp64 theta -> accurate fp32 sincos
    float sn[4], cs[4];
#pragma unroll
    for (int c = 0; c < 4; c++)
        sincosf((float)((double)s * g_tab.fd[j0 + c]), &sn[c], &cs[c]);
    const float4 p = make_float4(sn[0], cs[1], sn[2], cs[3]);

    const size_t bstride = (size_t)PE_S * PE_D4;
    const size_t base    = (size_t)s * PE_D4 + d4;
    const float4* __restrict__ xp = x   + base;
    float4* __restrict__       op = out + base;

    // front-batch the 4 batch loads, then add, then store
    float4 v[PE_B];
#pragma unroll
    for (int b = 0; b < PE_B; b++) v[b] = xp[(size_t)b * bstride];
#pragma unroll
    for (int b = 0; b < PE_B; b++) {
        v[b].x += p.x; v[b].y += p.y; v[b].z += p.z; v[b].w += p.w;
    }
#pragma unroll
    for (int b = 0; b < PE_B; b++) op[(size_t)b * bstride] = v[b];
}

extern "C" void kernel_launch(void* const* d_in, const int* in_sizes, int n_in,
                              void* d_out, int out_size) {
    (void)in_sizes; (void)n_in; (void)out_size;
    const float4* x = (const float4*)d_in[0];
    float4* out = (float4*)d_out;
    position_encoder_kernel<<<PE_S / PE_ROWS, 512>>>(x, out);
}